// round 14
// baseline (speedup 1.0000x reference)
#include <cuda_runtime.h>
#include <cstdint>

#define N_MAX 50176

__device__ float g_agg[(size_t)N_MAX * 128];   // attention-weighted neigh rows
__device__ float g_wa[128];                    // W  @ a[0:64]
__device__ float g_w2a[128];                   // W2 @ a[64:128]

// ---------------------------------------------------------------------------
// packed f32x2 helpers
// ---------------------------------------------------------------------------
__device__ __forceinline__ unsigned long long pack2(float lo, float hi) {
    unsigned long long r;
    asm("mov.b64 %0, {%1, %2};" : "=l"(r) : "f"(lo), "f"(hi));
    return r;
}
__device__ __forceinline__ void ffma2(unsigned long long& acc,
                                      unsigned long long a,
                                      unsigned long long b) {
    asm("fma.rn.f32x2 %0, %1, %2, %0;" : "+l"(acc) : "l"(a), "l"(b));
}
__device__ __forceinline__ float2 unpack2(unsigned long long v) {
    float lo, hi;
    asm("mov.b64 {%0, %1}, %2;" : "=f"(lo), "=f"(hi) : "l"(v));
    return make_float2(lo, hi);
}

// ---------------------------------------------------------------------------
// prep: g_wa = W @ a[0:64], g_w2a = W2 @ a[64:128]. One 256-thread block.
// ---------------------------------------------------------------------------
__global__ void prep_kernel(const float* __restrict__ W,
                            const float* __restrict__ W2,
                            const float* __restrict__ a)
{
    const int t = threadIdx.x;            // 0..255
    const int d = t & 127;
    const float* M  = (t < 128) ? W : W2;
    const float* av = (t < 128) ? a : a + 64;
    float s = 0.f;
#pragma unroll
    for (int j = 0; j < 16; ++j) {
        float4 m = ((const float4*)(M + d * 64))[j];
        float4 q = ((const float4*)av)[j];
        s += m.x * q.x + m.y * q.y + m.z * q.z + m.w * q.w;
    }
    if (t < 128) g_wa[d] = s; else g_w2a[d] = s;
}

// ---------------------------------------------------------------------------
// GEMM: (N x 128) @ (128 x 64) -> out[:, coff:coff+64].
// 128 threads, 128x64 tile, 8x8 per thread (row-paired f32x2 accumulators).
// K processed in two 64-wide halves; A staged transposed [k][row], W staged
// pre-duplicated as (w,w) f32x2 pairs. smem 66.5KB -> 3 CTAs/SM.
// ---------------------------------------------------------------------------
#define GP 130   // sAt row pad (floats, even for LDS.64 alignment)
#define WP 65    // sWd row pad (b64 units)

__global__ __launch_bounds__(128, 3)
void gemm_kernel(const float* __restrict__ Ain,
                 const float* __restrict__ Wm,
                 float* __restrict__ out, int N, int coff, int useAgg)
{
    extern __shared__ float smraw[];
    float* sAt = smraw;                                        // 64*130 floats
    unsigned long long* sWd = (unsigned long long*)(smraw + 64 * GP); // 64*65

    const int tid  = threadIdx.x;
    const int row0 = blockIdx.x * 128;
    const float* A = useAgg ? (const float*)g_agg : Ain;

    const int rb = (tid >> 3) * 8;   // 0..120
    const int cb = (tid & 7) * 8;    // 0..56

    unsigned long long acc[4][8];
#pragma unroll
    for (int p = 0; p < 4; ++p)
#pragma unroll
        for (int c = 0; c < 8; ++c) acc[p][c] = 0ULL;

#pragma unroll
    for (int h = 0; h < 2; ++h) {
        const int k0 = h * 64;
        // ---- stage A transposed: sAt[k][row] ----
#pragma unroll
        for (int it = 0; it < 16; ++it) {
            int f4  = it * 128 + tid;
            int row = f4 >> 4;
            int k4  = f4 & 15;
            float4 v = make_float4(0.f, 0.f, 0.f, 0.f);
            if (row0 + row < N)
                v = ((const float4*)A)[(size_t)(row0 + row) * 32 + (k0 >> 2) + k4];
            sAt[(4 * k4 + 0) * GP + row] = v.x;
            sAt[(4 * k4 + 1) * GP + row] = v.y;
            sAt[(4 * k4 + 2) * GP + row] = v.z;
            sAt[(4 * k4 + 3) * GP + row] = v.w;
        }
        // ---- stage W duplicated: sWd[k][c] = (w, w) ----
#pragma unroll
        for (int it = 0; it < 8; ++it) {
            int f4 = it * 128 + tid;
            int kk = f4 >> 4;
            int c4 = f4 & 15;
            float4 v = ((const float4*)Wm)[(size_t)(k0 + kk) * 16 + c4];
            unsigned long long* d = sWd + kk * WP + c4 * 4;
            d[0] = pack2(v.x, v.x);
            d[1] = pack2(v.y, v.y);
            d[2] = pack2(v.z, v.z);
            d[3] = pack2(v.w, v.w);
        }
        __syncthreads();

#pragma unroll 4
        for (int k = 0; k < 64; ++k) {
            unsigned long long av[4];
#pragma unroll
            for (int p = 0; p < 4; ++p)
                av[p] = *(const unsigned long long*)(sAt + k * GP + rb + 2 * p);
            unsigned long long w[8];
#pragma unroll
            for (int c = 0; c < 8; ++c) w[c] = sWd[k * WP + cb + c];
#pragma unroll
            for (int p = 0; p < 4; ++p)
#pragma unroll
                for (int c = 0; c < 8; ++c) ffma2(acc[p][c], av[p], w[c]);
        }
        __syncthreads();
    }

    // ---- epilogue: acc[p][c] = (row rb+2p, row rb+2p+1) ----
#pragma unroll
    for (int p = 0; p < 4; ++p) {
        float2 u[8];
#pragma unroll
        for (int c = 0; c < 8; ++c) u[c] = unpack2(acc[p][c]);
        int r0g = row0 + rb + 2 * p;
        if (r0g < N) {
            float* dst = out + (size_t)r0g * 160 + coff + cb;
            ((float4*)dst)[0] = make_float4(u[0].x, u[1].x, u[2].x, u[3].x);
            ((float4*)dst)[1] = make_float4(u[4].x, u[5].x, u[6].x, u[7].x);
        }
        if (r0g + 1 < N) {
            float* dst = out + (size_t)(r0g + 1) * 160 + coff + cb;
            ((float4*)dst)[0] = make_float4(u[0].y, u[1].y, u[2].y, u[3].y);
            ((float4*)dst)[1] = make_float4(u[4].y, u[5].y, u[6].y, u[7].y);
        }
    }
}

// ---------------------------------------------------------------------------
// attn: one warp per node. Score phase = per-lane partials (dims 4*lid..+3)
// + 16-shuffle butterfly fold -> score[lid&15]; softmax + shuffle-broadcast
// aggregation. Writes g_agg and out[:, 128:160].
// ---------------------------------------------------------------------------
__global__ __launch_bounds__(256, 2)
void attn_kernel(const float* __restrict__ input,
                 const float* __restrict__ neigh,
                 const float* __restrict__ edge,
                 const float* __restrict__ a,
                 float* __restrict__ out, int N)
{
    extern __shared__ float sm[];
    float* s_w2a = sm;            // 128
    float* s_wa  = sm + 128;      // 128
    float* s_ae  = sm + 256;      // 32
    float* wbase = sm + 288;      // 8 warps x 2560

    const int tid = threadIdx.x;
    const int wid = tid >> 5;
    const int lid = tid & 31;

    if (tid < 128) { s_w2a[tid] = g_w2a[tid]; s_wa[tid] = g_wa[tid]; }
    if (tid >= 128 && tid < 160) s_ae[tid - 128] = a[tid];

    float* sn = wbase + wid * 2560;   // 16 x 128 neigh tile
    float* se = sn + 2048;            // 16 x 32  edge tile
    __syncthreads();

    const int n = blockIdx.x * 8 + wid;
    if (n >= N) return;

    // ---- stage tiles (coalesced float4) ----
    const float4* nsrc = (const float4*)(neigh + (size_t)n * 2048);
    float4*       ndst = (float4*)sn;
#pragma unroll
    for (int i = 0; i < 16; ++i) ndst[lid + 32 * i] = nsrc[lid + 32 * i];
    const float4* esrc = (const float4*)(edge + (size_t)n * 512);
    float4*       edst = (float4*)se;
#pragma unroll
    for (int i = 0; i < 4; ++i)  edst[lid + 32 * i] = esrc[lid + 32 * i];

    // ---- x score term: input[n] . g_wa (independent of staged tiles) ----
    float sx = 0.f;
#pragma unroll
    for (int k = 0; k < 4; ++k) {
        int d = lid + 32 * k;
        sx += input[(size_t)n * 128 + d] * s_wa[d];
    }
#pragma unroll
    for (int o = 16; o; o >>= 1) sx += __shfl_xor_sync(0xffffffffu, sx, o);

    __syncwarp();

    // ---- per-lane score partials over dims 4lid..4lid+3 (+ edge dim lid) ----
    const float4 w2 = *(const float4*)(s_w2a + lid * 4);
    const float  ae = s_ae[lid];
    float v[16];
#pragma unroll
    for (int s = 0; s < 16; ++s) {
        float4 nv = *(const float4*)(sn + s * 128 + lid * 4);
        v[s] = nv.x * w2.x + nv.y * w2.y + nv.z * w2.z + nv.w * w2.w
             + se[s * 32 + lid] * ae;
    }
    // ---- butterfly fold: 16 values -> score[lid&15] on each lane ----
#pragma unroll
    for (int st = 0; st < 4; ++st) {
        const int m = 1 << st;
        const int b = (lid >> st) & 1;
#pragma unroll
        for (int j = 0; j < (8 >> st); ++j) {
            float keep = b ? v[2 * j + 1] : v[2 * j];
            float send = b ? v[2 * j]     : v[2 * j + 1];
            v[j] = keep + __shfl_xor_sync(0xffffffffu, send, m);
        }
    }
    float sc = sx + v[0] + __shfl_xor_sync(0xffffffffu, v[0], 16);
    float ev = sc > 0.f ? sc : 0.8f * sc;              // leaky relu, ALPHA=0.8

    // ---- softmax over 16 (duplicated across halves) ----
    float mx = ev;
#pragma unroll
    for (int o = 8; o; o >>= 1) mx = fmaxf(mx, __shfl_xor_sync(0xffffffffu, mx, o));
    float p = __expf(ev - mx);
    float sum = p;
#pragma unroll
    for (int o = 8; o; o >>= 1) sum += __shfl_xor_sync(0xffffffffu, sum, o);
    const float att = p / sum;                          // lane s holds att[s]

    // ---- aggregation + h_edge (att broadcast via shuffle) ----
    float4 acc = make_float4(0.f, 0.f, 0.f, 0.f);
    float  eacc = 0.f;
#pragma unroll
    for (int s = 0; s < 16; ++s) {
        float at = __shfl_sync(0xffffffffu, att, s);
        float4 nv = *(const float4*)(sn + s * 128 + lid * 4);
        acc.x += at * nv.x; acc.y += at * nv.y;
        acc.z += at * nv.z; acc.w += at * nv.w;
        eacc  += at * se[s * 32 + lid];
    }
    ((float4*)g_agg)[(size_t)n * 32 + lid] = acc;
    out[(size_t)n * 160 + 128 + lid] = eacc;
}

// ---------------------------------------------------------------------------
extern "C" void kernel_launch(void* const* d_in, const int* in_sizes, int n_in,
                              void* d_out, int out_size)
{
    const float* input = (const float*)d_in[0];
    const float* neigh = (const float*)d_in[1];
    const float* edge  = (const float*)d_in[2];
    const float* W     = (const float*)d_in[3];
    const float* W2    = (const float*)d_in[4];
    const float* a     = (const float*)d_in[5];
    float* out = (float*)d_out;

    const int N = in_sizes[0] / 128;

    const int smemA = (288 + 8 * 2560) * 4;          // 83,072 B
    const int smemB = (64 * GP) * 4 + (64 * WP) * 8; // 66,560 B

    static cudaStream_t s1 = nullptr;
    static cudaEvent_t evA = nullptr, evB = nullptr;
    static bool inited = false;
    if (!inited) {
        cudaFuncSetAttribute(attn_kernel, cudaFuncAttributeMaxDynamicSharedMemorySize, smemA);
        cudaFuncSetAttribute(gemm_kernel, cudaFuncAttributeMaxDynamicSharedMemorySize, smemB);
        if (cudaStreamCreateWithFlags(&s1, cudaStreamNonBlocking) != cudaSuccess) s1 = nullptr;
        cudaEventCreateWithFlags(&evA, cudaEventDisableTiming);
        cudaEventCreateWithFlags(&evB, cudaEventDisableTiming);
        inited = true;
    }

    const int gblocks = (N + 127) / 128;
    cudaStream_t side = s1 ? s1 : (cudaStream_t)0;

    // fork: gemm_x (independent) runs on side stream, concurrent with prep+attn
    if (s1) { cudaEventRecord(evA, 0); cudaStreamWaitEvent(s1, evA, 0); }
    gemm_kernel<<<gblocks, 128, smemB, side>>>(input, W, out, N, 0, 0);

    // main stream: prep -> attn -> gemm_h
    prep_kernel<<<1, 256>>>(W, W2, a);
    attn_kernel<<<(N + 7) / 8, 256, smemA>>>(input, neigh, edge, a, out, N);
    gemm_kernel<<<gblocks, 128, smemB>>>(nullptr, W2, out, N, 64, 1);

    // join
    if (s1) { cudaEventRecord(evB, s1); cudaStreamWaitEvent(0, evB, 0); }
}

// round 15
// speedup vs baseline: 1.0004x; 1.0004x over previous
#include <cuda_runtime.h>
#include <cstdint>

#define N_MAX 50176

__device__ float g_agg[(size_t)N_MAX * 128];   // attention-weighted neigh rows
__device__ float g_wa[128];                    // W  @ a[0:64]
__device__ float g_w2a[128];                   // W2 @ a[64:128]

// ---------------------------------------------------------------------------
// packed f32x2 helpers
// ---------------------------------------------------------------------------
__device__ __forceinline__ unsigned long long pack2(float lo, float hi) {
    unsigned long long r;
    asm("mov.b64 %0, {%1, %2};" : "=l"(r) : "f"(lo), "f"(hi));
    return r;
}
__device__ __forceinline__ void ffma2(unsigned long long& acc,
                                      unsigned long long a,
                                      unsigned long long b) {
    asm("fma.rn.f32x2 %0, %1, %2, %0;" : "+l"(acc) : "l"(a), "l"(b));
}
__device__ __forceinline__ float2 unpack2(unsigned long long v) {
    float lo, hi;
    asm("mov.b64 {%0, %1}, %2;" : "=f"(lo), "=f"(hi) : "l"(v));
    return make_float2(lo, hi);
}

// ---------------------------------------------------------------------------
// prep: g_wa = W @ a[0:64], g_w2a = W2 @ a[64:128]. One 256-thread block.
// ---------------------------------------------------------------------------
__global__ void prep_kernel(const float* __restrict__ W,
                            const float* __restrict__ W2,
                            const float* __restrict__ a)
{
    const int t = threadIdx.x;            // 0..255
    const int d = t & 127;
    const float* M  = (t < 128) ? W : W2;
    const float* av = (t < 128) ? a : a + 64;
    float s = 0.f;
#pragma unroll
    for (int j = 0; j < 16; ++j) {
        float4 m = ((const float4*)(M + d * 64))[j];
        float4 q = ((const float4*)av)[j];
        s += m.x * q.x + m.y * q.y + m.z * q.z + m.w * q.w;
    }
    if (t < 128) g_wa[d] = s; else g_w2a[d] = s;
}

// ---------------------------------------------------------------------------
// GEMM: (N x 128) @ (128 x 64) -> out[:, coff:coff+64].
// 128 threads, 128x64 tile, 8x8 per thread (row-paired f32x2 accumulators).
// K processed in two 64-wide halves; A staged transposed [k][row], W staged
// pre-duplicated as (w,w) f32x2 pairs. smem 66.5KB -> 3 CTAs/SM.
// ---------------------------------------------------------------------------
#define GP 130   // sAt row pad (floats, even for LDS.64 alignment)
#define WP 65    // sWd row pad (b64 units)

__global__ __launch_bounds__(128, 3)
void gemm_kernel(const float* __restrict__ Ain,
                 const float* __restrict__ Wm,
                 float* __restrict__ out, int N, int coff, int useAgg)
{
    extern __shared__ float smraw[];
    float* sAt = smraw;                                        // 64*130 floats
    unsigned long long* sWd = (unsigned long long*)(smraw + 64 * GP); // 64*65

    const int tid  = threadIdx.x;
    const int row0 = blockIdx.x * 128;
    const float* A = useAgg ? (const float*)g_agg : Ain;

    const int rb = (tid >> 3) * 8;   // 0..120
    const int cb = (tid & 7) * 8;    // 0..56

    unsigned long long acc[4][8];
#pragma unroll
    for (int p = 0; p < 4; ++p)
#pragma unroll
        for (int c = 0; c < 8; ++c) acc[p][c] = 0ULL;

#pragma unroll
    for (int h = 0; h < 2; ++h) {
        const int k0 = h * 64;
        // ---- stage A transposed: sAt[k][row] ----
#pragma unroll
        for (int it = 0; it < 16; ++it) {
            int f4  = it * 128 + tid;
            int row = f4 >> 4;
            int k4  = f4 & 15;
            float4 v = make_float4(0.f, 0.f, 0.f, 0.f);
            if (row0 + row < N)
                v = ((const float4*)A)[(size_t)(row0 + row) * 32 + (k0 >> 2) + k4];
            sAt[(4 * k4 + 0) * GP + row] = v.x;
            sAt[(4 * k4 + 1) * GP + row] = v.y;
            sAt[(4 * k4 + 2) * GP + row] = v.z;
            sAt[(4 * k4 + 3) * GP + row] = v.w;
        }
        // ---- stage W duplicated: sWd[k][c] = (w, w) ----
#pragma unroll
        for (int it = 0; it < 8; ++it) {
            int f4 = it * 128 + tid;
            int kk = f4 >> 4;
            int c4 = f4 & 15;
            float4 v = ((const float4*)Wm)[(size_t)(k0 + kk) * 16 + c4];
            unsigned long long* d = sWd + kk * WP + c4 * 4;
            d[0] = pack2(v.x, v.x);
            d[1] = pack2(v.y, v.y);
            d[2] = pack2(v.z, v.z);
            d[3] = pack2(v.w, v.w);
        }
        __syncthreads();

#pragma unroll 4
        for (int k = 0; k < 64; ++k) {
            unsigned long long av[4];
#pragma unroll
            for (int p = 0; p < 4; ++p)
                av[p] = *(const unsigned long long*)(sAt + k * GP + rb + 2 * p);
            unsigned long long w[8];
#pragma unroll
            for (int c = 0; c < 8; ++c) w[c] = sWd[k * WP + cb + c];
#pragma unroll
            for (int p = 0; p < 4; ++p)
#pragma unroll
                for (int c = 0; c < 8; ++c) ffma2(acc[p][c], av[p], w[c]);
        }
        __syncthreads();
    }

    // ---- epilogue: acc[p][c] = (row rb+2p, row rb+2p+1) ----
#pragma unroll
    for (int p = 0; p < 4; ++p) {
        float2 u[8];
#pragma unroll
        for (int c = 0; c < 8; ++c) u[c] = unpack2(acc[p][c]);
        int r0g = row0 + rb + 2 * p;
        if (r0g < N) {
            float* dst = out + (size_t)r0g * 160 + coff + cb;
            ((float4*)dst)[0] = make_float4(u[0].x, u[1].x, u[2].x, u[3].x);
            ((float4*)dst)[1] = make_float4(u[4].x, u[5].x, u[6].x, u[7].x);
        }
        if (r0g + 1 < N) {
            float* dst = out + (size_t)(r0g + 1) * 160 + coff + cb;
            ((float4*)dst)[0] = make_float4(u[0].y, u[1].y, u[2].y, u[3].y);
            ((float4*)dst)[1] = make_float4(u[4].y, u[5].y, u[6].y, u[7].y);
        }
    }
}

// ---------------------------------------------------------------------------
// attn: one warp per node. Score phase = per-lane partials (dims 4*lid..+3)
// + 16-shuffle butterfly fold -> score[lid&15]; softmax + shuffle-broadcast
// aggregation. Writes g_agg and out[:, 128:160].
// ---------------------------------------------------------------------------
__global__ __launch_bounds__(256, 2)
void attn_kernel(const float* __restrict__ input,
                 const float* __restrict__ neigh,
                 const float* __restrict__ edge,
                 const float* __restrict__ a,
                 float* __restrict__ out, int N)
{
    extern __shared__ float sm[];
    float* s_w2a = sm;            // 128
    float* s_wa  = sm + 128;      // 128
    float* s_ae  = sm + 256;      // 32
    float* wbase = sm + 288;      // 8 warps x 2560

    const int tid = threadIdx.x;
    const int wid = tid >> 5;
    const int lid = tid & 31;

    if (tid < 128) { s_w2a[tid] = g_w2a[tid]; s_wa[tid] = g_wa[tid]; }
    if (tid >= 128 && tid < 160) s_ae[tid - 128] = a[tid];

    float* sn = wbase + wid * 2560;   // 16 x 128 neigh tile
    float* se = sn + 2048;            // 16 x 32  edge tile
    __syncthreads();

    const int n = blockIdx.x * 8 + wid;
    if (n >= N) return;

    // ---- stage tiles (coalesced float4) ----
    const float4* nsrc = (const float4*)(neigh + (size_t)n * 2048);
    float4*       ndst = (float4*)sn;
#pragma unroll
    for (int i = 0; i < 16; ++i) ndst[lid + 32 * i] = nsrc[lid + 32 * i];
    const float4* esrc = (const float4*)(edge + (size_t)n * 512);
    float4*       edst = (float4*)se;
#pragma unroll
    for (int i = 0; i < 4; ++i)  edst[lid + 32 * i] = esrc[lid + 32 * i];

    // ---- x score term: input[n] . g_wa (independent of staged tiles) ----
    float sx = 0.f;
#pragma unroll
    for (int k = 0; k < 4; ++k) {
        int d = lid + 32 * k;
        sx += input[(size_t)n * 128 + d] * s_wa[d];
    }
#pragma unroll
    for (int o = 16; o; o >>= 1) sx += __shfl_xor_sync(0xffffffffu, sx, o);

    __syncwarp();

    // ---- per-lane score partials over dims 4lid..4lid+3 (+ edge dim lid) ----
    const float4 w2 = *(const float4*)(s_w2a + lid * 4);
    const float  ae = s_ae[lid];
    float v[16];
#pragma unroll
    for (int s = 0; s < 16; ++s) {
        float4 nv = *(const float4*)(sn + s * 128 + lid * 4);
        v[s] = nv.x * w2.x + nv.y * w2.y + nv.z * w2.z + nv.w * w2.w
             + se[s * 32 + lid] * ae;
    }
    // ---- butterfly fold: 16 values -> score[lid&15] on each lane ----
#pragma unroll
    for (int st = 0; st < 4; ++st) {
        const int m = 1 << st;
        const int b = (lid >> st) & 1;
#pragma unroll
        for (int j = 0; j < (8 >> st); ++j) {
            float keep = b ? v[2 * j + 1] : v[2 * j];
            float send = b ? v[2 * j]     : v[2 * j + 1];
            v[j] = keep + __shfl_xor_sync(0xffffffffu, send, m);
        }
    }
    float sc = sx + v[0] + __shfl_xor_sync(0xffffffffu, v[0], 16);
    float ev = sc > 0.f ? sc : 0.8f * sc;              // leaky relu, ALPHA=0.8

    // ---- softmax over 16 (duplicated across halves) ----
    float mx = ev;
#pragma unroll
    for (int o = 8; o; o >>= 1) mx = fmaxf(mx, __shfl_xor_sync(0xffffffffu, mx, o));
    float p = __expf(ev - mx);
    float sum = p;
#pragma unroll
    for (int o = 8; o; o >>= 1) sum += __shfl_xor_sync(0xffffffffu, sum, o);
    const float att = p / sum;                          // lane s holds att[s]

    // ---- aggregation + h_edge (att broadcast via shuffle) ----
    float4 acc = make_float4(0.f, 0.f, 0.f, 0.f);
    float  eacc = 0.f;
#pragma unroll
    for (int s = 0; s < 16; ++s) {
        float at = __shfl_sync(0xffffffffu, att, s);
        float4 nv = *(const float4*)(sn + s * 128 + lid * 4);
        acc.x += at * nv.x; acc.y += at * nv.y;
        acc.z += at * nv.z; acc.w += at * nv.w;
        eacc  += at * se[s * 32 + lid];
    }
    ((float4*)g_agg)[(size_t)n * 32 + lid] = acc;
    out[(size_t)n * 160 + 128 + lid] = eacc;
}

// ---------------------------------------------------------------------------
extern "C" void kernel_launch(void* const* d_in, const int* in_sizes, int n_in,
                              void* d_out, int out_size)
{
    const float* input = (const float*)d_in[0];
    const float* neigh = (const float*)d_in[1];
    const float* edge  = (const float*)d_in[2];
    const float* W     = (const float*)d_in[3];
    const float* W2    = (const float*)d_in[4];
    const float* a     = (const float*)d_in[5];
    float* out = (float*)d_out;

    const int N = in_sizes[0] / 128;

    const int smemA = (288 + 8 * 2560) * 4;          // 83,072 B
    const int smemB = (64 * GP) * 4 + (64 * WP) * 8; // 66,560 B

    static cudaStream_t s1 = nullptr;
    static cudaEvent_t evA = nullptr, evB = nullptr;
    static bool inited = false;
    if (!inited) {
        cudaFuncSetAttribute(attn_kernel, cudaFuncAttributeMaxDynamicSharedMemorySize, smemA);
        cudaFuncSetAttribute(gemm_kernel, cudaFuncAttributeMaxDynamicSharedMemorySize, smemB);
        if (cudaStreamCreateWithFlags(&s1, cudaStreamNonBlocking) != cudaSuccess) s1 = nullptr;
        cudaEventCreateWithFlags(&evA, cudaEventDisableTiming);
        cudaEventCreateWithFlags(&evB, cudaEventDisableTiming);
        inited = true;
    }

    const int gblocks = (N + 127) / 128;
    cudaStream_t side = s1 ? s1 : (cudaStream_t)0;

    // fork: gemm_x (independent) runs on side stream, concurrent with prep+attn
    if (s1) { cudaEventRecord(evA, 0); cudaStreamWaitEvent(s1, evA, 0); }
    gemm_kernel<<<gblocks, 128, smemB, side>>>(input, W, out, N, 0, 0);

    // main stream: prep -> attn -> gemm_h
    prep_kernel<<<1, 256>>>(W, W2, a);
    attn_kernel<<<(N + 7) / 8, 256, smemA>>>(input, neigh, edge, a, out, N);
    gemm_kernel<<<gblocks, 128, smemB>>>(nullptr, W2, out, N, 64, 1);

    // join
    if (s1) { cudaEventRecord(evB, s1); cudaStreamWaitEvent(0, evB, 0); }
}